// round 2
// baseline (speedup 1.0000x reference)
#include <cuda_runtime.h>

#define THREADS 256
#define BT 32
#define TT 30
#define FF 16

// ---------------- shared memory layout (float offsets) ----------------
// weight region (reused between phases):
#define W1T    0        // [80][256]  = 20480   (phase 1)
#define W2T    20480    // [96][128]  = 12288   (phase 1)
#define W3T    0        // [32][128]  = 4096    (phase 2)
#define W4T    4096     // [96][256]  = 24576   (phase 2)
#define WOUTT  28672    // [64][16]   = 1024    (phase 2)
#define WIH3T  29696    // [32][128]  = 4096    (phase 2)
// biases (persistent):
#define B1o    33792    // 256
#define B2o    34048    // 128
#define B3o    34176    // 128
#define B4o    34304    // 256
#define BOUTo  34560    // 16
// state:
#define Zo     34576    // [32][258] = 8256
#define IN1o   42832    // [80][33]  = 2640  (x:k<16, h1:k>=16)
#define C1o    45472    // [64][33]  = 2112  (c1 / c4)
#define IN2o   47584    // [96][33]  = 3168  (h1,h2 / h3,h4)
#define C2o    50752    // [32][33]  = 1056  (c2 / c3)
#define ZIN3o  51808    // [32][130] = 4160
#define SHFLOATS 55968  // 223872 bytes

__device__ __forceinline__ float sigx(float x) {
    float e; asm("ex2.approx.f32 %0, %1;" : "=f"(e) : "f"(x * -1.4426950408889634f));
    float r; asm("rcp.approx.f32 %0, %1;" : "=f"(r) : "f"(1.0f + e));
    return r;
}
__device__ __forceinline__ float tanhx(float x) { return fmaf(2.0f, sigx(2.0f * x), -1.0f); }

// z[l][g0..g0+GPW) += sum_k W[k][g] * in[k][l]   (weights transposed in shared,
// gate-pairs packed into f32x2; per-row input broadcast into both halves)
template<int K, int NG>
__device__ __forceinline__ void gemm(float* sh, int woff, int inoff, int outoff,
                                     int outstride, int w, int l)
{
    constexpr int GPW = NG / 8;   // gates per warp
    constexpr int NP  = GPW / 2;  // f32x2 accumulators
    const int g0 = GPW * w;
    unsigned long long acc[NP];
#pragma unroll
    for (int p = 0; p < NP; p++) acc[p] = 0ull;
    const float* in = sh + inoff + l;
    const float* W  = sh + woff + g0;
#pragma unroll 4
    for (int k = 0; k < K; k++) {
        float h = in[k * 33];
        unsigned int hb = __float_as_uint(h);
        unsigned long long h2;
        asm("mov.b64 %0, {%1, %1};" : "=l"(h2) : "r"(hb));
        const ulonglong2* wr = reinterpret_cast<const ulonglong2*>(W + k * NG);
#pragma unroll
        for (int q = 0; q < NP / 2; q++) {
            ulonglong2 wv = wr[q];
            asm("fma.rn.f32x2 %0, %1, %2, %0;" : "+l"(acc[2 * q])     : "l"(wv.x), "l"(h2));
            asm("fma.rn.f32x2 %0, %1, %2, %0;" : "+l"(acc[2 * q + 1]) : "l"(wv.y), "l"(h2));
        }
    }
    unsigned long long* zo =
        reinterpret_cast<unsigned long long*>(sh + outoff + l * outstride + g0);
#pragma unroll
    for (int p = 0; p < NP; p++) zo[p] = acc[p];
}

// gate order i,f,g,o (PyTorch / reference convention)
template<int H>
__device__ __forceinline__ void lstm_act(float* sh, int boff, int coff,
                                         int h1off, int h2off, int zin3, int tid)
{
    const int u = tid % H;
    constexpr int NR = (32 * H) / THREADS;
    const int r0 = (tid / H) * NR;
    const float bi = sh[boff + u],       bf = sh[boff + H + u];
    const float bg = sh[boff + 2*H + u], bo = sh[boff + 3*H + u];
#pragma unroll
    for (int i = 0; i < NR; i++) {
        const int r = r0 + i;
        const float* zr = sh + Zo + r * 258;
        float zi = zr[u] + bi;
        float zf = zr[H + u] + bf;
        float zg = zr[2*H + u] + bg;
        float zq = zr[3*H + u] + bo;
        if (zin3 >= 0) {
            const float* q = sh + zin3 + r * 130;
            zi += q[u]; zf += q[H + u]; zg += q[2*H + u]; zq += q[3*H + u];
        }
        float c  = sh[coff + u * 33 + r];
        float cn = sigx(zf) * c + sigx(zi) * tanhx(zg);
        float hn = sigx(zq) * tanhx(cn);
        sh[coff  + u * 33 + r] = cn;
        sh[h1off + u * 33 + r] = hn;
        if (h2off >= 0) sh[h2off + u * 33 + r] = hn;
    }
}

__global__ void __launch_bounds__(THREADS, 1)
lstm_ae(const float* __restrict__ x,
        const float* __restrict__ Wih1, const float* __restrict__ Whh1, const float* __restrict__ b1,
        const float* __restrict__ Wih2, const float* __restrict__ Whh2, const float* __restrict__ b2,
        const float* __restrict__ Wih3, const float* __restrict__ Whh3, const float* __restrict__ b3,
        const float* __restrict__ Wih4, const float* __restrict__ Whh4, const float* __restrict__ b4,
        const float* __restrict__ Wout, const float* __restrict__ bout,
        float* __restrict__ out)
{
    extern __shared__ float sh[];
    const int tid = threadIdx.x;
    const int w = tid >> 5, l = tid & 31;
    const long row0 = (long)blockIdx.x * BT;

    // ---- phase-1 weights (transposed [k][g]) + biases, zero state ----
    for (int i = tid; i < 20480; i += THREADS) {
        int k = i >> 8, g = i & 255;
        sh[W1T + i] = (k < 16) ? Wih1[g * 16 + k] : Whh1[g * 64 + (k - 16)];
    }
    for (int i = tid; i < 12288; i += THREADS) {
        int k = i >> 7, g = i & 127;
        sh[W2T + i] = (k < 64) ? Wih2[g * 64 + k] : Whh2[g * 32 + (k - 64)];
    }
    if (tid < 256) sh[B1o + tid] = b1[tid];
    if (tid < 128) sh[B2o + tid] = b2[tid];
    if (tid < 128) sh[B3o + tid] = b3[tid];
    if (tid < 256) sh[B4o + tid] = b4[tid];
    if (tid < 16)  sh[BOUTo + tid] = bout[tid];
    for (int i = tid; i < 2640; i += THREADS) sh[IN1o + i] = 0.f;
    for (int i = tid; i < 2112; i += THREADS) sh[C1o  + i] = 0.f;
    for (int i = tid; i < 3168; i += THREADS) sh[IN2o + i] = 0.f;
    for (int i = tid; i < 1056; i += THREADS) sh[C2o  + i] = 0.f;
    __syncthreads();

    // ---- phase 1: encoder LSTM(64) + LSTM(32), fused per step ----
    for (int t = 0; t < TT; t++) {
        for (int i = tid; i < 512; i += THREADS) {
            int r = i >> 4, f = i & 15;
            sh[IN1o + f * 33 + r] = x[(row0 + r) * (TT * FF) + t * FF + f];
        }
        __syncthreads();
        gemm<80, 256>(sh, W1T, IN1o, Zo, 258, w, l);
        __syncthreads();
        lstm_act<64>(sh, B1o, C1o, IN1o + 16 * 33, IN2o, -1, tid);
        __syncthreads();
        gemm<96, 128>(sh, W2T, IN2o, Zo, 258, w, l);
        __syncthreads();
        lstm_act<32>(sh, B2o, C2o, IN2o + 64 * 33, -1, -1, tid);
        // no sync needed: next x-stage touches disjoint region; top sync orders h2
    }
    __syncthreads();

    // ---- phase-2 weights (overwrite phase-1 region) ----
    for (int i = tid; i < 4096; i += THREADS) {
        int k = i >> 7, g = i & 127;
        sh[W3T + i] = Whh3[g * 32 + k];
    }
    for (int i = tid; i < 24576; i += THREADS) {
        int k = i >> 8, g = i & 255;
        sh[W4T + i] = (k < 32) ? Wih4[g * 32 + k] : Whh4[g * 64 + (k - 32)];
    }
    for (int i = tid; i < 1024; i += THREADS) {
        int j = i >> 4, f = i & 15;
        sh[WOUTT + i] = Wout[f * 64 + j];
    }
    for (int i = tid; i < 4096; i += THREADS) {
        int k = i >> 7, g = i & 127;
        sh[WIH3T + i] = Wih3[g * 32 + k];
    }
    __syncthreads();

    // zin3 = Wih3 @ latent, computed once (decoder input is constant over t)
    gemm<32, 128>(sh, WIH3T, IN2o + 64 * 33, ZIN3o, 130, w, l);
    __syncthreads();
    // zero decoder state: in4 (= IN2 region: h3 k<32, h4 k>=32), c3 (=C2), c4 (=C1)
    for (int i = tid; i < 3168; i += THREADS) sh[IN2o + i] = 0.f;
    for (int i = tid; i < 2112; i += THREADS) sh[C1o  + i] = 0.f;
    for (int i = tid; i < 1056; i += THREADS) sh[C2o  + i] = 0.f;
    __syncthreads();

    // ---- phase 2: decoder LSTM(32) + LSTM(64) + out projection ----
    for (int t = 0; t < TT; t++) {
        gemm<32, 128>(sh, W3T, IN2o, Zo, 258, w, l);        // Whh3 @ h3
        __syncthreads();
        lstm_act<32>(sh, B3o, C2o, IN2o, -1, ZIN3o, tid);   // += zin3 + b3
        __syncthreads();
        gemm<96, 256>(sh, W4T, IN2o, Zo, 258, w, l);        // [Wih4;Whh4] @ [h3;h4]
        __syncthreads();
        lstm_act<64>(sh, B4o, C1o, IN2o + 32 * 33, -1, -1, tid);
        __syncthreads();
        // output projection y[r][f] = Wout @ h4 + bout
        {
            const int f = tid & 15, rb = tid >> 4;
#pragma unroll
            for (int p = 0; p < 2; p++) {
                const int r = rb + 16 * p;
                float acc = sh[BOUTo + f];
                const float* h4 = sh + IN2o + 32 * 33 + r;
#pragma unroll 8
                for (int j = 0; j < 64; j++)
                    acc = fmaf(sh[WOUTT + j * 16 + f], h4[j * 33], acc);
                out[(row0 + r) * (TT * FF) + t * FF + f] = acc;
            }
        }
        // no sync needed: next gemm3 writes Zo (readers done), reads h3 (sync'd),
        // out-proj reads h4 which is only rewritten after two more syncs
    }
}

extern "C" void kernel_launch(void* const* d_in, const int* in_sizes, int n_in,
                              void* d_out, int out_size)
{
    const float* x    = (const float*)d_in[0];
    const float* Wih1 = (const float*)d_in[1];
    const float* Whh1 = (const float*)d_in[2];
    const float* b1   = (const float*)d_in[3];
    const float* Wih2 = (const float*)d_in[4];
    const float* Whh2 = (const float*)d_in[5];
    const float* b2   = (const float*)d_in[6];
    const float* Wih3 = (const float*)d_in[7];
    const float* Whh3 = (const float*)d_in[8];
    const float* b3   = (const float*)d_in[9];
    const float* Wih4 = (const float*)d_in[10];
    const float* Whh4 = (const float*)d_in[11];
    const float* b4   = (const float*)d_in[12];
    const float* Wout = (const float*)d_in[13];
    const float* bout = (const float*)d_in[14];
    float* out = (float*)d_out;

    cudaFuncSetAttribute(lstm_ae, cudaFuncAttributeMaxDynamicSharedMemorySize,
                         SHFLOATS * (int)sizeof(float));
    lstm_ae<<<8192 / BT, THREADS, SHFLOATS * sizeof(float)>>>(
        x, Wih1, Whh1, b1, Wih2, Whh2, b2, Wih3, Whh3, b3,
        Wih4, Whh4, b4, Wout, bout, out);
}

// round 3
// speedup vs baseline: 1.4844x; 1.4844x over previous
#include <cuda_runtime.h>

#define THREADS 256
#define TT 30

typedef unsigned long long ull;

// ---------------- shared memory layout (float offsets) ----------------
// weight region (phase-overlaid):
#define WT     0        // P1: W1' [80][256]=20480 ; P2: W3' [32][128]=4096
#define W2o    20480    // P1: W2' [96][128]=12288
#define W4o    4096     // P2: W4' [96][256]=24576
#define WOUTo  28672    // P2: Wout' [64][16]=1024
#define WIH3o  29696    // P2: Wih3' [32][128]=4096   (ends 33792)
// biases (interleaved [u][gate]):
#define B1o    33792    // 256
#define B2o    34048    // 128
#define B3o    34176    // 128
#define B4o    34304    // 256
#define BOo    34560    // 16
// state (all [unit][row], stride 64, double-buffered):
#define XINo   34576    // 2 x [16][64] = 2048
#define H1o    36624    // 2 x [64][64] = 8192   (P2: h4)
#define H2o    44816    // 2 x [32][64] = 4096   (P2: h3)
#define ZIN3o  48912    // [128][64] = 8192  (Wih3@latent + b3, interleaved gates)
#define SHF    57104    // 228416 bytes

__device__ __forceinline__ void ffma2(ull &acc, ull a, ull b){
    asm("fma.rn.f32x2 %0, %1, %2, %0;" : "+l"(acc) : "l"(a), "l"(b));
}
__device__ __forceinline__ ull bcast2(float w){
    ull r; asm("mov.b64 %0, {%1, %1};" : "=l"(r) : "f"(w)); return r;
}
__device__ __forceinline__ ull pack2(float x, float y){
    ull r; asm("mov.b64 %0, {%1, %2};" : "=l"(r) : "f"(x), "f"(y)); return r;
}
__device__ __forceinline__ float2 unpack2(ull v){
    float2 f; asm("mov.b64 {%0, %1}, %2;" : "=f"(f.x), "=f"(f.y) : "l"(v)); return f;
}
__device__ __forceinline__ float sigx(float x){
    float e; asm("ex2.approx.f32 %0, %1;" : "=f"(e) : "f"(x * -1.4426950408889634f));
    float r; asm("rcp.approx.f32 %0, %1;" : "=f"(r) : "f"(1.0f + e));
    return r;
}
__device__ __forceinline__ float tanhx(float x){ return fmaf(2.0f, sigx(2.0f*x), -1.0f); }

// acc[j][g][p] = z for unit (u0+j), gate g, row-pair (r0+2p, r0+2p+1)
// in:  [k][row] stride 64 ; W: pre-offset by u0*4, rows of NG, interleaved [u][g]
template<int NU, int NG>
__device__ __forceinline__ void accum(const float* __restrict__ in,
                                      const float* __restrict__ W,
                                      int K, ull (&acc)[NU][4][4], int r0)
{
#pragma unroll 4
    for (int k = 0; k < K; k++) {
        ulonglong2 hA = *reinterpret_cast<const ulonglong2*>(in + k*64 + r0);
        ulonglong2 hB = *reinterpret_cast<const ulonglong2*>(in + k*64 + r0 + 4);
        ull hp0 = hA.x, hp1 = hA.y, hp2 = hB.x, hp3 = hB.y;
#pragma unroll
        for (int j = 0; j < NU; j++) {
            float4 w = *reinterpret_cast<const float4*>(W + k*NG + j*4);
            ull w0 = bcast2(w.x), w1 = bcast2(w.y), w2 = bcast2(w.z), w3 = bcast2(w.w);
            ffma2(acc[j][0][0], w0, hp0); ffma2(acc[j][0][1], w0, hp1);
            ffma2(acc[j][0][2], w0, hp2); ffma2(acc[j][0][3], w0, hp3);
            ffma2(acc[j][1][0], w1, hp0); ffma2(acc[j][1][1], w1, hp1);
            ffma2(acc[j][1][2], w1, hp2); ffma2(acc[j][1][3], w1, hp3);
            ffma2(acc[j][2][0], w2, hp0); ffma2(acc[j][2][1], w2, hp1);
            ffma2(acc[j][2][2], w2, hp2); ffma2(acc[j][2][3], w2, hp3);
            ffma2(acc[j][3][0], w3, hp0); ffma2(acc[j][3][1], w3, hp1);
            ffma2(acc[j][3][2], w3, hp2); ffma2(acc[j][3][3], w3, hp3);
        }
    }
}

template<int NU>
__device__ __forceinline__ void init_acc(ull (&acc)[NU][4][4], const ull (&b)[NU][4]){
#pragma unroll
    for (int j = 0; j < NU; j++)
#pragma unroll
        for (int g = 0; g < 4; g++)
#pragma unroll
            for (int p = 0; p < 4; p++) acc[j][g][p] = b[j][g];
}

// in-register LSTM activation (gate order i,f,g,o); c stays in registers.
// hdst pre-offset by u0*64.
template<int NU>
__device__ __forceinline__ void act_store(ull (&acc)[NU][4][4], float (&c)[NU][8],
                                          float* hdst, int r0)
{
#pragma unroll
    for (int j = 0; j < NU; j++)
#pragma unroll
    for (int p = 0; p < 4; p++) {
        float2 zi = unpack2(acc[j][0][p]);
        float2 zf = unpack2(acc[j][1][p]);
        float2 zg = unpack2(acc[j][2][p]);
        float2 zo = unpack2(acc[j][3][p]);
        float cn0 = sigx(zf.x)*c[j][2*p]   + sigx(zi.x)*tanhx(zg.x);
        float cn1 = sigx(zf.y)*c[j][2*p+1] + sigx(zi.y)*tanhx(zg.y);
        float h0 = sigx(zo.x)*tanhx(cn0);
        float h1 = sigx(zo.y)*tanhx(cn1);
        c[j][2*p] = cn0; c[j][2*p+1] = cn1;
        *reinterpret_cast<ull*>(hdst + j*64 + r0 + 2*p) = pack2(h0, h1);
    }
}

__global__ void __launch_bounds__(THREADS, 1)
lstm_ae(const float* __restrict__ x,
        const float* __restrict__ Wih1, const float* __restrict__ Whh1, const float* __restrict__ b1,
        const float* __restrict__ Wih2, const float* __restrict__ Whh2, const float* __restrict__ b2,
        const float* __restrict__ Wih3, const float* __restrict__ Whh3, const float* __restrict__ b3,
        const float* __restrict__ Wih4, const float* __restrict__ Whh4, const float* __restrict__ b4,
        const float* __restrict__ Wout, const float* __restrict__ bout,
        float* __restrict__ out)
{
    extern __shared__ float sh[];
    const int tid = threadIdx.x;
    const long row0 = (long)blockIdx.x * 64;

    const int u0a = (tid >> 3) * 2;       // H=64 layers: units u0a, u0a+1
    const int u0b = (tid >> 3);           // H=32 layers: unit u0b
    const int r0  = (tid & 7) * 8;        // 8 rows per thread

    // ---- phase-1 weights (interleaved [k][u][g]) + biases ----
    for (int i = tid; i < 20480; i += THREADS) {
        int k = i >> 8, j = i & 255, u = j >> 2, g = j & 3, row = g * 64 + u;
        sh[WT + i] = (k < 16) ? Wih1[row * 16 + k] : Whh1[row * 64 + (k - 16)];
    }
    for (int i = tid; i < 12288; i += THREADS) {
        int k = i >> 7, j = i & 127, u = j >> 2, g = j & 3, row = g * 32 + u;
        sh[W2o + i] = (k < 64) ? Wih2[row * 64 + k] : Whh2[row * 32 + (k - 64)];
    }
    if (tid < 256) { int u = tid >> 2, g = tid & 3; sh[B1o + tid] = b1[g * 64 + u]; }
    if (tid < 128) { int u = tid >> 2, g = tid & 3; sh[B2o + tid] = b2[g * 32 + u]; }
    if (tid < 128) { int u = tid >> 2, g = tid & 3; sh[B3o + tid] = b3[g * 32 + u]; }
    if (tid < 256) { int u = tid >> 2, g = tid & 3; sh[B4o + tid] = b4[g * 64 + u]; }
    if (tid < 16)  sh[BOo + tid] = bout[tid];
    // zero prev-state buffers (buf 0)
    for (int i = tid; i < 4096; i += THREADS) sh[H1o + i] = 0.f;
    for (int i = tid; i < 2048; i += THREADS) sh[H2o + i] = 0.f;
    // load x(t=0) into xin buf 0 (transpose to [f][row])
    {
        int f0 = (tid & 3) * 4, r = tid >> 2;
        float4 gx = *reinterpret_cast<const float4*>(x + (row0 + r) * (TT * 16) + f0);
        sh[XINo + (f0 + 0) * 64 + r] = gx.x;
        sh[XINo + (f0 + 1) * 64 + r] = gx.y;
        sh[XINo + (f0 + 2) * 64 + r] = gx.z;
        sh[XINo + (f0 + 3) * 64 + r] = gx.w;
    }
    __syncthreads();

    // bias packs + cell states in registers
    ull b1p[2][4], b2p[1][4];
#pragma unroll
    for (int j = 0; j < 2; j++)
#pragma unroll
        for (int g = 0; g < 4; g++) b1p[j][g] = bcast2(sh[B1o + (u0a + j) * 4 + g]);
#pragma unroll
    for (int g = 0; g < 4; g++) b2p[0][g] = bcast2(sh[B2o + u0b * 4 + g]);

    float c1[2][8], c2[1][8];
#pragma unroll
    for (int j = 0; j < 2; j++)
#pragma unroll
        for (int q = 0; q < 8; q++) c1[j][q] = 0.f;
#pragma unroll
    for (int q = 0; q < 8; q++) c2[0][q] = 0.f;

    // ---- phase 1: encoder LSTM(64) -> LSTM(32) ----
    for (int t = 0; t < TT; t++) {
        const int p = t & 1;
        // prefetch x(t+1) into xin[p^1]
        if (t + 1 < TT) {
            int f0 = (tid & 3) * 4, r = tid >> 2;
            float4 gx = *reinterpret_cast<const float4*>(
                x + (row0 + r) * (TT * 16) + (t + 1) * 16 + f0);
            float* xb = sh + XINo + (p ^ 1) * 1024;
            xb[(f0 + 0) * 64 + r] = gx.x;
            xb[(f0 + 1) * 64 + r] = gx.y;
            xb[(f0 + 2) * 64 + r] = gx.z;
            xb[(f0 + 3) * 64 + r] = gx.w;
        }
        // L1
        {
            ull acc[2][4][4];
            init_acc<2>(acc, b1p);
            accum<2, 256>(sh + XINo + p * 1024, sh + WT + u0a * 4, 16, acc, r0);
            accum<2, 256>(sh + H1o + p * 4096, sh + WT + 16 * 256 + u0a * 4, 64, acc, r0);
            act_store<2>(acc, c1, sh + H1o + (p ^ 1) * 4096 + u0a * 64, r0);
        }
        __syncthreads();
        // L2
        {
            ull acc[1][4][4];
            init_acc<1>(acc, b2p);
            accum<1, 128>(sh + H1o + (p ^ 1) * 4096, sh + W2o + u0b * 4, 64, acc, r0);
            accum<1, 128>(sh + H2o + p * 2048, sh + W2o + 64 * 128 + u0b * 4, 32, acc, r0);
            act_store<1>(acc, c2, sh + H2o + (p ^ 1) * 2048 + u0b * 64, r0);
        }
        __syncthreads();
    }
    // latent = h2 final, lives in H2 buf 0 (t=29: p=1 wrote buf 0)

    // ---- phase-2 weights (overwrite phase-1 region) ----
    for (int i = tid; i < 4096; i += THREADS) {
        int k = i >> 7, j = i & 127, u = j >> 2, g = j & 3, row = g * 32 + u;
        sh[WT + i] = Whh3[row * 32 + k];
    }
    for (int i = tid; i < 24576; i += THREADS) {
        int k = i >> 8, j = i & 255, u = j >> 2, g = j & 3, row = g * 64 + u;
        sh[W4o + i] = (k < 32) ? Wih4[row * 32 + k] : Whh4[row * 64 + (k - 32)];
    }
    for (int i = tid; i < 1024; i += THREADS) {
        int jr = i >> 4, f = i & 15;
        sh[WOUTo + i] = Wout[f * 64 + jr];
    }
    for (int i = tid; i < 4096; i += THREADS) {
        int k = i >> 7, j = i & 127, u = j >> 2, g = j & 3, row = g * 32 + u;
        sh[WIH3o + i] = Wih3[row * 32 + k];
    }
    __syncthreads();

    // zin3 = Wih3 @ latent + b3 (decoder input constant over t), store interleaved [u*4+g][r]
    {
        ull b3p[1][4];
#pragma unroll
        for (int g = 0; g < 4; g++) b3p[0][g] = bcast2(sh[B3o + u0b * 4 + g]);
        ull acc[1][4][4];
        init_acc<1>(acc, b3p);
        accum<1, 128>(sh + H2o, sh + WIH3o + u0b * 4, 32, acc, r0);
        __syncthreads();   // all reads of latent done before H2 reuse as h3
#pragma unroll
        for (int g = 0; g < 4; g++)
#pragma unroll
            for (int pp = 0; pp < 4; pp++)
                *reinterpret_cast<ull*>(sh + ZIN3o + (u0b * 4 + g) * 64 + r0 + 2 * pp) =
                    acc[0][g][pp];
        // zero decoder prev-state buffers (buf 0): h3 (H2), h4 (H1)
        for (int i = tid; i < 2048; i += THREADS) sh[H2o + i] = 0.f;
        for (int i = tid; i < 4096; i += THREADS) sh[H1o + i] = 0.f;
    }
    __syncthreads();

    ull b4p[2][4];
#pragma unroll
    for (int j = 0; j < 2; j++)
#pragma unroll
        for (int g = 0; g < 4; g++) b4p[j][g] = bcast2(sh[B4o + (u0a + j) * 4 + g]);
    const float boutf = sh[BOo + (tid & 15)];

    float c3[1][8], c4[2][8];
#pragma unroll
    for (int q = 0; q < 8; q++) c3[0][q] = 0.f;
#pragma unroll
    for (int j = 0; j < 2; j++)
#pragma unroll
        for (int q = 0; q < 8; q++) c4[j][q] = 0.f;

    // ---- phase 2: decoder LSTM(32) -> LSTM(64) -> projection ----
    for (int t = 0; t < TT; t++) {
        const int p = t & 1;
        // L3: acc init from zin3 (bias folded)
        {
            ull acc[1][4][4];
#pragma unroll
            for (int g = 0; g < 4; g++)
#pragma unroll
                for (int pp = 0; pp < 4; pp++)
                    acc[0][g][pp] = *reinterpret_cast<const ull*>(
                        sh + ZIN3o + (u0b * 4 + g) * 64 + r0 + 2 * pp);
            accum<1, 128>(sh + H2o + p * 2048, sh + WT + u0b * 4, 32, acc, r0);
            act_store<1>(acc, c3, sh + H2o + (p ^ 1) * 2048 + u0b * 64, r0);
        }
        __syncthreads();
        // L4
        {
            ull acc[2][4][4];
            init_acc<2>(acc, b4p);
            accum<2, 256>(sh + H2o + (p ^ 1) * 2048, sh + W4o + u0a * 4, 32, acc, r0);
            accum<2, 256>(sh + H1o + p * 4096, sh + W4o + 32 * 256 + u0a * 4, 64, acc, r0);
            act_store<2>(acc, c4, sh + H1o + (p ^ 1) * 4096 + u0a * 64, r0);
        }
        __syncthreads();
        // output projection: y[r][f] = Wout@h4 + bout ; thread = (f, 4 rows)
        {
            const int f = tid & 15, rb = tid >> 4;
            const float* h4 = sh + H1o + (p ^ 1) * 4096;
            ull a0 = bcast2(boutf), a1 = a0;
#pragma unroll 8
            for (int j = 0; j < 64; j++) {
                ull w = bcast2(sh[WOUTo + j * 16 + f]);
                ull hq0 = *reinterpret_cast<const ull*>(h4 + j * 64 + rb * 4);
                ull hq1 = *reinterpret_cast<const ull*>(h4 + j * 64 + rb * 4 + 2);
                ffma2(a0, w, hq0);
                ffma2(a1, w, hq1);
            }
            float2 y01 = unpack2(a0), y23 = unpack2(a1);
            long ob = (row0 + rb * 4) * (TT * 16) + t * 16 + f;
            out[ob]                = y01.x;
            out[ob + TT * 16]      = y01.y;
            out[ob + 2 * TT * 16]  = y23.x;
            out[ob + 3 * TT * 16]  = y23.y;
        }
        // no extra sync: next L3 writes H2[p] (readers synced two barriers ago),
        // out-proj reads only H1[p^1] which next t never writes
    }
}

extern "C" void kernel_launch(void* const* d_in, const int* in_sizes, int n_in,
                              void* d_out, int out_size)
{
    const float* x    = (const float*)d_in[0];
    const float* Wih1 = (const float*)d_in[1];
    const float* Whh1 = (const float*)d_in[2];
    const float* b1   = (const float*)d_in[3];
    const float* Wih2 = (const float*)d_in[4];
    const float* Whh2 = (const float*)d_in[5];
    const float* b2   = (const float*)d_in[6];
    const float* Wih3 = (const float*)d_in[7];
    const float* Whh3 = (const float*)d_in[8];
    const float* b3   = (const float*)d_in[9];
    const float* Wih4 = (const float*)d_in[10];
    const float* Whh4 = (const float*)d_in[11];
    const float* b4   = (const float*)d_in[12];
    const float* Wout = (const float*)d_in[13];
    const float* bout = (const float*)d_in[14];
    float* out = (float*)d_out;

    cudaFuncSetAttribute(lstm_ae, cudaFuncAttributeMaxDynamicSharedMemorySize,
                         SHF * (int)sizeof(float));
    lstm_ae<<<128, THREADS, SHF * sizeof(float)>>>(
        x, Wih1, Whh1, b1, Wih2, Whh2, b2, Wih3, Whh3, b3,
        Wih4, Whh4, b4, Wout, bout, out);
}

// round 4
// speedup vs baseline: 1.6895x; 1.1381x over previous
#include <cuda_runtime.h>

#define THREADS 256
#define TT 30
#define RS 68   // row stride (swizzle padding)

typedef unsigned long long ull;

// ---------------- shared memory layout (float offsets) ----------------
#define WT     0        // P1: W1' [80][256]=20480 ; P2: W3' [32][128]=4096
#define W2o    20480    // P1: W2' [96][128]=12288
#define W4o    4096     // P2: W4' [96][256]=24576
#define WOUTo  28672    // P2: Wout' [64][16]=1024
#define WIH3o  29696    // P2: Wih3' [32][128]=4096   (ends 33792)
#define B1o    33792    // 256
#define B2o    34048    // 128
#define B3o    34176    // 128
#define B4o    34304    // 256
#define BOo    34560    // 16
// state [k][row] stride RS, rows swizzled: phys(r) = r + 4*(r>=32)
#define XINo   34576    // 2 x [16][68] = 2176
#define H1o    36752    // 2 x [64][68] = 8704   (P2: h4)
#define H2o    45456    // 2 x [32][68] = 4352   (P2: h3)
#define SHF    49808    // 199232 bytes

__device__ __forceinline__ void ffma2(ull &acc, ull a, ull b){
    asm("fma.rn.f32x2 %0, %1, %2, %0;" : "+l"(acc) : "l"(a), "l"(b));
}
__device__ __forceinline__ ull bcast2(float w){
    ull r; asm("mov.b64 %0, {%1, %1};" : "=l"(r) : "f"(w)); return r;
}
__device__ __forceinline__ ull pack2(float x, float y){
    ull r; asm("mov.b64 %0, {%1, %2};" : "=l"(r) : "f"(x), "f"(y)); return r;
}
__device__ __forceinline__ float2 unpack2(ull v){
    float2 f; asm("mov.b64 {%0, %1}, %2;" : "=f"(f.x), "=f"(f.y) : "l"(v)); return f;
}
__device__ __forceinline__ float sigx(float x){
    float e; asm("ex2.approx.f32 %0, %1;" : "=f"(e) : "f"(x * -1.4426950408889634f));
    float r; asm("rcp.approx.f32 %0, %1;" : "=f"(r) : "f"(1.0f + e));
    return r;
}
__device__ __forceinline__ float tanhx(float x){ return fmaf(2.0f, sigx(2.0f*x), -1.0f); }

// acc[j][g][p] += sum_k W[k][u][g] * in[k][pr0+2p..]
// in: [k][row] stride RS (pr0 = swizzled row base); W: pre-offset by u0*4
template<int NU, int NG>
__device__ __forceinline__ void accum(const float* __restrict__ in,
                                      const float* __restrict__ W,
                                      int K, ull (&acc)[NU][4][4], int pr0)
{
#pragma unroll 4
    for (int k = 0; k < K; k++) {
        ulonglong2 hA = *reinterpret_cast<const ulonglong2*>(in + k*RS + pr0);
        ulonglong2 hB = *reinterpret_cast<const ulonglong2*>(in + k*RS + pr0 + 4);
        ull hp0 = hA.x, hp1 = hA.y, hp2 = hB.x, hp3 = hB.y;
#pragma unroll
        for (int j = 0; j < NU; j++) {
            float4 w = *reinterpret_cast<const float4*>(W + k*NG + j*4);
            ull w0 = bcast2(w.x), w1 = bcast2(w.y), w2 = bcast2(w.z), w3 = bcast2(w.w);
            ffma2(acc[j][0][0], w0, hp0); ffma2(acc[j][0][1], w0, hp1);
            ffma2(acc[j][0][2], w0, hp2); ffma2(acc[j][0][3], w0, hp3);
            ffma2(acc[j][1][0], w1, hp0); ffma2(acc[j][1][1], w1, hp1);
            ffma2(acc[j][1][2], w1, hp2); ffma2(acc[j][1][3], w1, hp3);
            ffma2(acc[j][2][0], w2, hp0); ffma2(acc[j][2][1], w2, hp1);
            ffma2(acc[j][2][2], w2, hp2); ffma2(acc[j][2][3], w2, hp3);
            ffma2(acc[j][3][0], w3, hp0); ffma2(acc[j][3][1], w3, hp1);
            ffma2(acc[j][3][2], w3, hp2); ffma2(acc[j][3][3], w3, hp3);
        }
    }
}

template<int NU>
__device__ __forceinline__ void init_acc(ull (&acc)[NU][4][4], const ull (&b)[NU][4]){
#pragma unroll
    for (int j = 0; j < NU; j++)
#pragma unroll
        for (int g = 0; g < 4; g++)
#pragma unroll
            for (int p = 0; p < 4; p++) acc[j][g][p] = b[j][g];
}

// in-register LSTM activation (gate order i,f,g,o); c stays in registers.
template<int NU>
__device__ __forceinline__ void act_store(ull (&acc)[NU][4][4], float (&c)[NU][8],
                                          float* hdst, int pr0)
{
#pragma unroll
    for (int j = 0; j < NU; j++)
#pragma unroll
    for (int p = 0; p < 4; p++) {
        float2 zi = unpack2(acc[j][0][p]);
        float2 zf = unpack2(acc[j][1][p]);
        float2 zg = unpack2(acc[j][2][p]);
        float2 zo = unpack2(acc[j][3][p]);
        float cn0 = sigx(zf.x)*c[j][2*p]   + sigx(zi.x)*tanhx(zg.x);
        float cn1 = sigx(zf.y)*c[j][2*p+1] + sigx(zi.y)*tanhx(zg.y);
        float h0 = sigx(zo.x)*tanhx(cn0);
        float h1 = sigx(zo.y)*tanhx(cn1);
        c[j][2*p] = cn0; c[j][2*p+1] = cn1;
        *reinterpret_cast<ull*>(hdst + j*RS + pr0 + 2*p) = pack2(h0, h1);
    }
}

__global__ void __launch_bounds__(THREADS, 1)
lstm_ae(const float* __restrict__ x,
        const float* __restrict__ Wih1, const float* __restrict__ Whh1, const float* __restrict__ b1,
        const float* __restrict__ Wih2, const float* __restrict__ Whh2, const float* __restrict__ b2,
        const float* __restrict__ Wih3, const float* __restrict__ Whh3, const float* __restrict__ b3,
        const float* __restrict__ Wih4, const float* __restrict__ Whh4, const float* __restrict__ b4,
        const float* __restrict__ Wout, const float* __restrict__ bout,
        float* __restrict__ out)
{
    extern __shared__ float sh[];
    const int tid = threadIdx.x;
    const long row0 = (long)blockIdx.x * 64;

    const int u0a = (tid >> 3) * 2;           // H=64 layers: units u0a, u0a+1
    const int u0b = (tid >> 3);               // H=32 layers: unit u0b
    const int r0  = (tid & 7) * 8;            // 8 rows per thread
    const int pr0 = r0 + ((r0 & 32) >> 3);    // swizzled base

    // ---- phase-1 weights (interleaved [k][u][g]) + biases ----
    for (int i = tid; i < 20480; i += THREADS) {
        int k = i >> 8, j = i & 255, u = j >> 2, g = j & 3, row = g * 64 + u;
        sh[WT + i] = (k < 16) ? Wih1[row * 16 + k] : Whh1[row * 64 + (k - 16)];
    }
    for (int i = tid; i < 12288; i += THREADS) {
        int k = i >> 7, j = i & 127, u = j >> 2, g = j & 3, row = g * 32 + u;
        sh[W2o + i] = (k < 64) ? Wih2[row * 64 + k] : Whh2[row * 32 + (k - 64)];
    }
    if (tid < 256) { int u = tid >> 2, g = tid & 3; sh[B1o + tid] = b1[g * 64 + u]; }
    if (tid < 128) { int u = tid >> 2, g = tid & 3; sh[B2o + tid] = b2[g * 32 + u]; }
    if (tid < 128) { int u = tid >> 2, g = tid & 3; sh[B3o + tid] = b3[g * 32 + u]; }
    if (tid < 256) { int u = tid >> 2, g = tid & 3; sh[B4o + tid] = b4[g * 64 + u]; }
    if (tid < 16)  sh[BOo + tid] = bout[tid];
    for (int i = tid; i < 4352; i += THREADS) sh[H1o + i] = 0.f;   // h1 buf0
    for (int i = tid; i < 2176; i += THREADS) sh[H2o + i] = 0.f;   // h2 buf0
    {
        int f0 = (tid & 3) * 4, r = tid >> 2;
        int pr = r + ((r & 32) >> 3);
        float4 gx = *reinterpret_cast<const float4*>(x + (row0 + r) * (TT * 16) + f0);
        sh[XINo + (f0 + 0) * RS + pr] = gx.x;
        sh[XINo + (f0 + 1) * RS + pr] = gx.y;
        sh[XINo + (f0 + 2) * RS + pr] = gx.z;
        sh[XINo + (f0 + 3) * RS + pr] = gx.w;
    }
    __syncthreads();

    ull b1p[2][4], b2p[1][4];
#pragma unroll
    for (int j = 0; j < 2; j++)
#pragma unroll
        for (int g = 0; g < 4; g++) b1p[j][g] = bcast2(sh[B1o + (u0a + j) * 4 + g]);
#pragma unroll
    for (int g = 0; g < 4; g++) b2p[0][g] = bcast2(sh[B2o + u0b * 4 + g]);

    float c1[2][8], c2[1][8];
#pragma unroll
    for (int j = 0; j < 2; j++)
#pragma unroll
        for (int q = 0; q < 8; q++) c1[j][q] = 0.f;
#pragma unroll
    for (int q = 0; q < 8; q++) c2[0][q] = 0.f;

    // ---- phase 1: encoder LSTM(64) -> LSTM(32) ----
    for (int t = 0; t < TT; t++) {
        const int p = t & 1;
        if (t + 1 < TT) {   // prefetch x(t+1)
            int f0 = (tid & 3) * 4, r = tid >> 2;
            int pr = r + ((r & 32) >> 3);
            float4 gx = *reinterpret_cast<const float4*>(
                x + (row0 + r) * (TT * 16) + (t + 1) * 16 + f0);
            float* xb = sh + XINo + (p ^ 1) * (16 * RS);
            xb[(f0 + 0) * RS + pr] = gx.x;
            xb[(f0 + 1) * RS + pr] = gx.y;
            xb[(f0 + 2) * RS + pr] = gx.z;
            xb[(f0 + 3) * RS + pr] = gx.w;
        }
        {   // L1
            ull acc[2][4][4];
            init_acc<2>(acc, b1p);
            accum<2, 256>(sh + XINo + p * (16 * RS), sh + WT + u0a * 4, 16, acc, pr0);
            accum<2, 256>(sh + H1o + p * (64 * RS), sh + WT + 16 * 256 + u0a * 4, 64, acc, pr0);
            act_store<2>(acc, c1, sh + H1o + (p ^ 1) * (64 * RS) + u0a * RS, pr0);
        }
        __syncthreads();
        {   // L2
            ull acc[1][4][4];
            init_acc<1>(acc, b2p);
            accum<1, 128>(sh + H1o + (p ^ 1) * (64 * RS), sh + W2o + u0b * 4, 64, acc, pr0);
            accum<1, 128>(sh + H2o + p * (32 * RS), sh + W2o + 64 * 128 + u0b * 4, 32, acc, pr0);
            act_store<1>(acc, c2, sh + H2o + (p ^ 1) * (32 * RS) + u0b * RS, pr0);
        }
        __syncthreads();
    }
    // latent = h2 final, in H2 buf 0 (t=29: p=1 wrote buf 0)

    // ---- phase-2 weights ----
    for (int i = tid; i < 4096; i += THREADS) {
        int k = i >> 7, j = i & 127, u = j >> 2, g = j & 3, row = g * 32 + u;
        sh[WT + i] = Whh3[row * 32 + k];
    }
    for (int i = tid; i < 24576; i += THREADS) {
        int k = i >> 8, j = i & 255, u = j >> 2, g = j & 3, row = g * 64 + u;
        sh[W4o + i] = (k < 32) ? Wih4[row * 32 + k] : Whh4[row * 64 + (k - 32)];
    }
    for (int i = tid; i < 1024; i += THREADS) {
        int jr = i >> 4, f = i & 15;
        sh[WOUTo + i] = Wout[f * 64 + jr];
    }
    for (int i = tid; i < 4096; i += THREADS) {
        int k = i >> 7, j = i & 127, u = j >> 2, g = j & 3, row = g * 32 + u;
        sh[WIH3o + i] = Wih3[row * 32 + k];
    }
    __syncthreads();

    // zin3 = Wih3 @ latent + b3 (constant over t) -> kept in registers
    ull zin3[1][4][4];
    {
        ull b3p[1][4];
#pragma unroll
        for (int g = 0; g < 4; g++) b3p[0][g] = bcast2(sh[B3o + u0b * 4 + g]);
        init_acc<1>(zin3, b3p);
        accum<1, 128>(sh + H2o, sh + WIH3o + u0b * 4, 32, zin3, pr0);
        __syncthreads();   // latent reads done before H2 reuse as h3
        for (int i = tid; i < 2176; i += THREADS) sh[H2o + i] = 0.f;  // h3 buf0
        for (int i = tid; i < 4352; i += THREADS) sh[H1o + i] = 0.f;  // h4 buf0
    }
    __syncthreads();

    ull b4p[2][4];
#pragma unroll
    for (int j = 0; j < 2; j++)
#pragma unroll
        for (int g = 0; g < 4; g++) b4p[j][g] = bcast2(sh[B4o + (u0a + j) * 4 + g]);
    const float boutf = sh[BOo + (tid & 15)];

    float c3[1][8], c4[2][8];
#pragma unroll
    for (int q = 0; q < 8; q++) c3[0][q] = 0.f;
#pragma unroll
    for (int j = 0; j < 2; j++)
#pragma unroll
        for (int q = 0; q < 8; q++) c4[j][q] = 0.f;

    // ---- phase 2: decoder LSTM(32) -> LSTM(64) -> projection ----
    for (int t = 0; t < TT; t++) {
        const int p = t & 1;
        {   // L3: acc init from zin3 registers (bias folded)
            ull acc[1][4][4];
#pragma unroll
            for (int g = 0; g < 4; g++)
#pragma unroll
                for (int pp = 0; pp < 4; pp++) acc[0][g][pp] = zin3[0][g][pp];
            accum<1, 128>(sh + H2o + p * (32 * RS), sh + WT + u0b * 4, 32, acc, pr0);
            act_store<1>(acc, c3, sh + H2o + (p ^ 1) * (32 * RS) + u0b * RS, pr0);
        }
        __syncthreads();
        {   // L4
            ull acc[2][4][4];
            init_acc<2>(acc, b4p);
            accum<2, 256>(sh + H2o + (p ^ 1) * (32 * RS), sh + W4o + u0a * 4, 32, acc, pr0);
            accum<2, 256>(sh + H1o + p * (64 * RS), sh + W4o + 32 * 256 + u0a * 4, 64, acc, pr0);
            act_store<2>(acc, c4, sh + H1o + (p ^ 1) * (64 * RS) + u0a * RS, pr0);
        }
        __syncthreads();
        {   // output projection: thread = (f, 4 rows)
            const int f = tid & 15, rb = tid >> 4;
            const int prb = rb * 4 + ((rb & 8) >> 1);
            const float* h4 = sh + H1o + (p ^ 1) * (64 * RS);
            ull a0 = bcast2(boutf), a1 = a0;
#pragma unroll 8
            for (int j = 0; j < 64; j++) {
                ull w = bcast2(sh[WOUTo + j * 16 + f]);
                ull hq0 = *reinterpret_cast<const ull*>(h4 + j * RS + prb);
                ull hq1 = *reinterpret_cast<const ull*>(h4 + j * RS + prb + 2);
                ffma2(a0, w, hq0);
                ffma2(a1, w, hq1);
            }
            float2 y01 = unpack2(a0), y23 = unpack2(a1);
            long ob = (row0 + rb * 4) * (TT * 16) + t * 16 + f;
            out[ob]               = y01.x;
            out[ob + TT * 16]     = y01.y;
            out[ob + 2 * TT * 16] = y23.x;
            out[ob + 3 * TT * 16] = y23.y;
        }
        // no extra sync: next L3 writes H2[p] (readers synced), out-proj reads
        // H1[p^1] which next t never writes
    }
}

extern "C" void kernel_launch(void* const* d_in, const int* in_sizes, int n_in,
                              void* d_out, int out_size)
{
    const float* x    = (const float*)d_in[0];
    const float* Wih1 = (const float*)d_in[1];
    const float* Whh1 = (const float*)d_in[2];
    const float* b1   = (const float*)d_in[3];
    const float* Wih2 = (const float*)d_in[4];
    const float* Whh2 = (const float*)d_in[5];
    const float* b2   = (const float*)d_in[6];
    const float* Wih3 = (const float*)d_in[7];
    const float* Whh3 = (const float*)d_in[8];
    const float* b3   = (const float*)d_in[9];
    const float* Wih4 = (const float*)d_in[10];
    const float* Whh4 = (const float*)d_in[11];
    const float* b4   = (const float*)d_in[12];
    const float* Wout = (const float*)d_in[13];
    const float* bout = (const float*)d_in[14];
    float* out = (float*)d_out;

    cudaFuncSetAttribute(lstm_ae, cudaFuncAttributeMaxDynamicSharedMemorySize,
                         SHF * (int)sizeof(float));
    lstm_ae<<<128, THREADS, SHF * sizeof(float)>>>(
        x, Wih1, Whh1, b1, Wih2, Whh2, b2, Wih3, Whh3, b3,
        Wih4, Whh4, b4, Wout, bout, out);
}